// round 9
// baseline (speedup 1.0000x reference)
#include <cuda_runtime.h>
#include <cuda_bf16.h>
#include <cuda_fp16.h>
#include <math.h>
#include <stdint.h>

#define HH 128
#define WW 128
#define HW 16384
#define BB 2

// ==================== helpers ====================
__device__ __forceinline__ uint32_t smem_u32(const void* p) {
    uint32_t a;
    asm("{ .reg .u64 t; cvta.to.shared.u64 t, %1; cvt.u32.u64 %0, t; }" : "=r"(a) : "l"(p));
    return a;
}
__device__ __forceinline__ void ldsm_x4(uint32_t* r, uint32_t addr) {
    asm volatile("ldmatrix.sync.aligned.m8n8.x4.shared.b16 {%0,%1,%2,%3}, [%4];"
        : "=r"(r[0]), "=r"(r[1]), "=r"(r[2]), "=r"(r[3]) : "r"(addr));
}
__device__ __forceinline__ void mma_bf16(float* c, const uint32_t* a, const uint32_t* b) {
    asm volatile(
        "mma.sync.aligned.m16n8k16.row.col.f32.bf16.bf16.f32 "
        "{%0,%1,%2,%3}, {%4,%5,%6,%7}, {%8,%9}, {%0,%1,%2,%3};"
        : "+f"(c[0]), "+f"(c[1]), "+f"(c[2]), "+f"(c[3])
        : "r"(a[0]), "r"(a[1]), "r"(a[2]), "r"(a[3]), "r"(b[0]), "r"(b[1]));
}
__device__ __forceinline__ uint32_t pack_bf(float v) {
    __nv_bfloat16 h = __float2bfloat16(v);
    float hf = __bfloat162float(h);
    __nv_bfloat16 l = __float2bfloat16(v - hf);
    return (uint32_t)__bfloat16_as_ushort(h) | ((uint32_t)__bfloat16_as_ushort(l) << 16);
}

// ==================== scratch globals ====================
// activations channels-last, packed bf16 hi|lo<<16: [b][cc][pix][64]
__device__ uint32_t g_in0 [BB*4*HW*64];
__device__ uint32_t g_h1  [BB*HW*64];
__device__ uint32_t g_h2  [BB*HW*64];
__device__ uint32_t g_h3  [BB*HW*64];
__device__ float4   g_offm[BB*144*HW];    // {oy, ox, mask, pad} per (g*9+k, pix)
__device__ __half   g_xt  [BB*128*HW];    // x fp16 channels-last [b][g][pix][8]
__device__ float    g_wt  [16*72*64];
__device__ float    g_part[4*BB*64*HW];
// weight tiles: [j][CoutP rows][72 cols] bf16, zero-padded
__device__ __align__(16) uint16_t g_w1h[36*64*72],  g_w1l[36*64*72];
__device__ __align__(16) uint16_t g_w2h[9*64*72],   g_w2l[9*64*72];
__device__ __align__(16) uint16_t g_w3h[9*64*72],   g_w3l[9*64*72];
__device__ __align__(16) uint16_t g_w4h[9*448*72],  g_w4l[9*448*72];

// ==================== prep kernels ====================
__global__ __launch_bounds__(256) void pack_in0_k(
    const float* __restrict__ ef, const float* __restrict__ f1, const float* __restrict__ f2)
{
    __shared__ uint32_t S[64*65];
    int cc = blockIdx.y, b = blockIdx.z;
    int pix0 = blockIdx.x * 64;
    int t = threadIdx.x;
    for (int i = t; i < 4096; i += 256) {
        int ch = i >> 6, px = i & 63;
        int g = cc*64 + ch;
        float v = 0.f;
        if (g < 192)      v = ef[((size_t)b*192 + g)*HW + pix0 + px];
        else if (g < 194) v = f1[((size_t)b*2 + (g-192))*HW + pix0 + px];
        else if (g < 196) v = f2[((size_t)b*2 + (g-194))*HW + pix0 + px];
        S[ch*65 + px] = pack_bf(v);
    }
    __syncthreads();
    for (int i = t; i < 4096; i += 256) {
        int px = i >> 6, ch = i & 63;
        g_in0[(((size_t)b*4 + cc)*HW + pix0 + px)*64 + ch] = S[ch*65 + px];
    }
}

__global__ __launch_bounds__(256) void wprep_k(
    const float* __restrict__ w, int Cin, int CoutR, int CoutP, int J,
    uint16_t* __restrict__ dh, uint16_t* __restrict__ dl)
{
    int idx = blockIdx.x*256 + threadIdx.x;
    if (idx >= J*CoutP*72) return;
    int col = idx % 72;
    int o   = (idx / 72) % CoutP;
    int j   = idx / (72*CoutP);
    int cc = j / 9, kk = j % 9;
    int cin = cc*64 + col;
    float v = (col < 64 && cin < Cin && o < CoutR) ? w[((size_t)o*Cin + cin)*9 + kk] : 0.f;
    __nv_bfloat16 h = __float2bfloat16(v);
    float hf = __bfloat162float(h);
    __nv_bfloat16 l = __float2bfloat16(v - hf);
    dh[idx] = __bfloat16_as_ushort(h);
    dl[idx] = __bfloat16_as_ushort(l);
}

// x -> fp16 channels-last [b][g][pix][8]
__global__ __launch_bounds__(256) void transp_x_k(const float* __restrict__ x)
{
    __shared__ float S[8*257];
    int g = blockIdx.y, b = blockIdx.z;
    int pix0 = blockIdx.x * 256;
    int t = threadIdx.x;
    for (int i = t; i < 2048; i += 256) {
        int ch = i >> 8, px = i & 255;
        S[ch*257 + px] = x[((size_t)(b*128 + g*8 + ch))*HW + pix0 + px];
    }
    __syncthreads();
    for (int i = t; i < 2048; i += 256) {
        int px = i >> 3, ch = i & 7;
        g_xt[(((size_t)(b*16 + g))*HW + pix0 + px)*8 + ch] = __float2half(S[ch*257 + px]);
    }
}

__global__ __launch_bounds__(256) void transp_w_k(const float* __restrict__ w)
{
    int i = blockIdx.x*256 + threadIdx.x;
    if (i >= 16*72*64) return;
    int o = i & 63, j = (i >> 6) % 72, g = i / (72*64);
    g_wt[i] = w[(size_t)o*1152 + (g*8 + j/9)*9 + (j % 9)];
}

// ==================== mma.sync conv3x3, M=128 (full row) ====================
// CTA = (b, y): M=128 px, N=64 cout chunk (blockIdx.y), 512 threads (4Mx4N warps).
// RT: 3 halo rows x 130 px x 64ch hi/lo (loaded once per cin-chunk, reused over ky,kx).
// 3-term bf16 split: D = Ah*Bh + Ah*Bl + Al*Bh, fp32 accumulate.
template<int CIN, int COUTP, int COUTR, int EPI>
__global__ __launch_bounds__(512) void convmma_k(
    const uint32_t* __restrict__ in, const uint16_t* __restrict__ wh,
    const uint16_t* __restrict__ wl, const float* __restrict__ bias,
    uint32_t* __restrict__ outp,
    const float* __restrict__ flow1, const float* __restrict__ flow2)
{
    extern __shared__ char sm[];
    constexpr int CCH = (CIN + 63) / 64;
    const int OFF_RTH = 0;           // 3*130*144 = 56160
    const int OFF_RTL = 56160;
    const int OFF_B   = 112320;      // 3 kx * (hi 9216 + lo 9216) = 55296

    uint32_t sbase = smem_u32(sm);
    int t = threadIdx.x, lane = t & 31, wid = t >> 5;
    int b = blockIdx.x >> 7, y = blockIdx.x & 127;
    int nc = blockIdx.y;
    int warp_m = wid & 3, warp_n = wid >> 2;

    float acc[2][2][4];
#pragma unroll
    for (int i = 0; i < 2; i++)
#pragma unroll
        for (int j2 = 0; j2 < 2; j2++)
#pragma unroll
            for (int k2 = 0; k2 < 4; k2++) acc[i][j2][k2] = 0.f;

    const int a_lane_row = warp_m*32 + (lane & 15);
    const int aseg = lane >> 4;
    const int b_row = warp_n*16 + (lane & 7) + ((lane >> 4) & 1)*8;
    const int bseg = (lane >> 3) & 1;

    for (int cc = 0; cc < CCH; cc++) {
        __syncthreads();   // previous cc's MMAs done before RT overwrite
        // RT load: 3 halo rows, split hi/lo via byte_perm
        const uint32_t* img = in + (((size_t)b*CCH + cc)*HW)*64;
        for (int i = t; i < 6240; i += 512) {
            int ry = i / 2080, rem = i % 2080;
            int p = rem >> 4, f = rem & 15;
            int r = y + ry - 1, x = p - 1;
            float4 v = make_float4(0.f, 0.f, 0.f, 0.f);
            if ((unsigned)r < (unsigned)HH && (unsigned)x < (unsigned)WW)
                v = ((const float4*)(img + (size_t)r*WW*64))[x*16 + f];
            uint32_t u0 = __float_as_uint(v.x), u1 = __float_as_uint(v.y);
            uint32_t u2 = __float_as_uint(v.z), u3 = __float_as_uint(v.w);
            uint2 hp = { __byte_perm(u0, u1, 0x5410), __byte_perm(u2, u3, 0x5410) };
            uint2 lp = { __byte_perm(u0, u1, 0x7632), __byte_perm(u2, u3, 0x7632) };
            *(uint2*)(sm + OFF_RTH + (ry*130 + p)*144 + f*8) = hp;
            *(uint2*)(sm + OFF_RTL + (ry*130 + p)*144 + f*8) = lp;
        }
        for (int ky = 0; ky < 3; ky++) {
            int r = y + ky - 1;
            if ((unsigned)r >= (unsigned)HH) continue;   // uniform skip
            __syncthreads();   // RT ready / previous ky MMAs done before B overwrite
            int j0 = cc*9 + ky*3;
#pragma unroll
            for (int kx = 0; kx < 3; kx++) {
                const float4* shp = (const float4*)(wh + ((size_t)(j0+kx)*COUTP + nc*64)*72);
                const float4* slp = (const float4*)(wl + ((size_t)(j0+kx)*COUTP + nc*64)*72);
                float4* dhp = (float4*)(sm + OFF_B + kx*18432);
                float4* dlp = (float4*)(sm + OFF_B + kx*18432 + 9216);
                for (int i = t; i < 576; i += 512) { dhp[i] = shp[i]; dlp[i] = slp[i]; }
            }
            __syncthreads();

            uint32_t rtH = sbase + OFF_RTH + ky*130*144;
            uint32_t rtL = sbase + OFF_RTL + ky*130*144;
#pragma unroll
            for (int kx = 0; kx < 3; kx++) {
                uint32_t aH0 = rtH + (uint32_t)(a_lane_row + kx)*144u;
                uint32_t aL0 = rtL + (uint32_t)(a_lane_row + kx)*144u;
                uint32_t bB  = sbase + OFF_B + kx*18432 + (uint32_t)b_row*144u;
#pragma unroll
                for (int ks = 0; ks < 4; ks++) {
                    uint32_t ka = (uint32_t)(ks*16 + aseg*8)*2;
                    uint32_t kb = (uint32_t)(ks*16 + bseg*8)*2;
                    uint32_t a_h[2][4], a_l[2][4], b_h[4], b_l[4];
                    ldsm_x4(a_h[0], aH0 + ka);
                    ldsm_x4(a_h[1], aH0 + 16*144 + ka);
                    ldsm_x4(a_l[0], aL0 + ka);
                    ldsm_x4(a_l[1], aL0 + 16*144 + ka);
                    ldsm_x4(b_h, bB + kb);
                    ldsm_x4(b_l, bB + 9216 + kb);
#pragma unroll
                    for (int mt = 0; mt < 2; mt++)
#pragma unroll
                        for (int nt = 0; nt < 2; nt++) {
                            mma_bf16(acc[mt][nt], a_h[mt], &b_h[nt*2]);
                            mma_bf16(acc[mt][nt], a_h[mt], &b_l[nt*2]);
                            mma_bf16(acc[mt][nt], a_l[mt], &b_h[nt*2]);
                        }
                }
            }
        }
    }

    __syncthreads();    // all ldsm done before smem reuse
    int g = lane >> 2, tq = lane & 3;
    if (EPI == 0) {
        uint32_t* OT = (uint32_t*)sm;       // [128 px][68]
#pragma unroll
        for (int mt = 0; mt < 2; mt++)
#pragma unroll
            for (int nt = 0; nt < 2; nt++)
#pragma unroll
                for (int rg = 0; rg < 4; rg++) {
                    int px = warp_m*32 + mt*16 + g + ((rg >> 1) ? 8 : 0);
                    int c  = warp_n*16 + nt*8 + tq*2 + (rg & 1);
                    float v = acc[mt][nt][rg] + bias[c];
                    v = v >= 0.f ? v : 0.1f*v;
                    OT[px*68 + c] = pack_bf(v);
                }
        __syncthreads();
        for (int i = t; i < 2048; i += 512) {
            int p = i >> 4, f = i & 15;
            ((float4*)outp)[((size_t)b*HW + y*WW + p)*16 + f] =
                *(const float4*)(sm + p*272 + f*16);
        }
    } else {
        float* dst = (float*)g_offm;
#pragma unroll
        for (int mt = 0; mt < 2; mt++)
#pragma unroll
            for (int nt = 0; nt < 2; nt++)
#pragma unroll
                for (int rg = 0; rg < 4; rg++) {
                    int px = warp_m*32 + mt*16 + g + ((rg >> 1) ? 8 : 0);
                    int c  = nc*64 + warp_n*16 + nt*8 + tq*2 + (rg & 1);
                    if (c >= COUTR) continue;
                    int pix = y*WW + px;
                    float v = acc[mt][nt][rg] + bias[c];
                    if (c < 288) {
                        int ch = c >> 1, comp = c & 1;
                        const float* fl = (c < 144) ? flow1 : flow2;
                        float add = fl[((size_t)b*2 + (1 - comp))*HW + pix];
                        dst[(((size_t)b*144 + ch)*HW + pix)*4 + comp] = 10.f*tanhf(v) + add;
                    } else {
                        int ch = c - 288;
                        dst[(((size_t)b*144 + ch)*HW + pix)*4 + 2] = 1.f/(1.f + expf(-v));
                    }
                }
    }
}

// ==================== modulated deformable conv (fp16 gather, fp32 GEMM) ====================
__global__ __launch_bounds__(256) void dcn4_k()
{
    __shared__ float s_val[72][64];
    __shared__ float s_w[72][64];
    int p0 = blockIdx.x << 6, b = blockIdx.y, q = blockIdx.z;
    int t = threadIdx.x;
    int o4 = (t & 15) << 2, pb = (t >> 4) << 2;
    float accs[16];
#pragma unroll
    for (int i = 0; i < 16; i++) accs[i] = 0.f;
    const float4* offm = g_offm + (size_t)b*144*HW;

    for (int gi = 0; gi < 4; gi++) {
        int g = q*4 + gi;
        {
            const float4* src = (const float4*)(g_wt + (size_t)g*4608);
            float4* dstw = (float4*)&s_w[0][0];
            for (int i = t; i < 1152; i += 256) dstw[i] = src[i];
        }
        const __half* gb = g_xt + ((size_t)(b*16 + g))*HW*8;
#pragma unroll
        for (int rep = 0; rep < 3; rep++) {
            int task = t + (rep << 8);
            if (task < 576) {
                int k = task >> 6, p = task & 63;
                int pix = p0 + p, y = pix >> 7, x = pix & 127;
                int ch = g*9 + k;
                float4 om = offm[(size_t)ch*HW + pix];
                float m = om.z;
                float py = (float)(y + (k/3) - 1) + om.x;
                float px = (float)(x + (k%3) - 1) + om.y;
                float fy = floorf(py), fx = floorf(px);
                float wy = py - fy, wx = px - fx;
                int y0 = (int)fy, x0 = (int)fx, y1 = y0 + 1, x1 = x0 + 1;
                float vy0 = ((unsigned)y0 < HH) ? 1.f : 0.f;
                float vy1 = ((unsigned)y1 < HH) ? 1.f : 0.f;
                float vx0 = ((unsigned)x0 < WW) ? 1.f : 0.f;
                float vx1 = ((unsigned)x1 < WW) ? 1.f : 0.f;
                int y0c = min(max(y0,0),HH-1), y1c = min(max(y1,0),HH-1);
                int x0c = min(max(x0,0),WW-1), x1c = min(max(x1,0),WW-1);
                float w00 = (1.f-wy)*(1.f-wx)*m*vy0*vx0;
                float w01 = (1.f-wy)*wx      *m*vy0*vx1;
                float w10 = wy*(1.f-wx)      *m*vy1*vx0;
                float w11 = wy*wx            *m*vy1*vx1;
                float v[8];
#pragma unroll
                for (int i = 0; i < 8; i++) v[i] = 0.f;
                uint4 r00 = *(const uint4*)(gb + ((size_t)(y0c*WW + x0c) << 3));
                uint4 r01 = *(const uint4*)(gb + ((size_t)(y0c*WW + x1c) << 3));
                uint4 r10 = *(const uint4*)(gb + ((size_t)(y1c*WW + x0c) << 3));
                uint4 r11 = *(const uint4*)(gb + ((size_t)(y1c*WW + x1c) << 3));
                const __half2* h00 = (const __half2*)&r00;
                const __half2* h01 = (const __half2*)&r01;
                const __half2* h10 = (const __half2*)&r10;
                const __half2* h11 = (const __half2*)&r11;
#pragma unroll
                for (int i = 0; i < 4; i++) {
                    float2 f00 = __half22float2(h00[i]);
                    float2 f01 = __half22float2(h01[i]);
                    float2 f10 = __half22float2(h10[i]);
                    float2 f11 = __half22float2(h11[i]);
                    v[i*2]   = w00*f00.x + w01*f01.x + w10*f10.x + w11*f11.x;
                    v[i*2+1] = w00*f00.y + w01*f01.y + w10*f10.y + w11*f11.y;
                }
#pragma unroll
                for (int c = 0; c < 8; c++) s_val[c*9 + k][p] = v[c];
            }
        }
        __syncthreads();

#pragma unroll 8
        for (int j = 0; j < 72; j++) {
            float4 wv = *(const float4*)&s_w[j][o4];
            float4 vv = *(const float4*)&s_val[j][pb];
            accs[0]  = fmaf(wv.x, vv.x, accs[0]);
            accs[1]  = fmaf(wv.x, vv.y, accs[1]);
            accs[2]  = fmaf(wv.x, vv.z, accs[2]);
            accs[3]  = fmaf(wv.x, vv.w, accs[3]);
            accs[4]  = fmaf(wv.y, vv.x, accs[4]);
            accs[5]  = fmaf(wv.y, vv.y, accs[5]);
            accs[6]  = fmaf(wv.y, vv.z, accs[6]);
            accs[7]  = fmaf(wv.y, vv.w, accs[7]);
            accs[8]  = fmaf(wv.z, vv.x, accs[8]);
            accs[9]  = fmaf(wv.z, vv.y, accs[9]);
            accs[10] = fmaf(wv.z, vv.z, accs[10]);
            accs[11] = fmaf(wv.z, vv.w, accs[11]);
            accs[12] = fmaf(wv.w, vv.x, accs[12]);
            accs[13] = fmaf(wv.w, vv.y, accs[13]);
            accs[14] = fmaf(wv.w, vv.z, accs[14]);
            accs[15] = fmaf(wv.w, vv.w, accs[15]);
        }
        __syncthreads();
    }

    float* pout = g_part + (((size_t)(q*BB + b))*64)*HW;
#pragma unroll
    for (int oi = 0; oi < 4; oi++)
#pragma unroll
        for (int pi = 0; pi < 4; pi++)
            pout[(size_t)(o4 + oi)*HW + p0 + pb + pi] = accs[oi*4 + pi];
}

__global__ __launch_bounds__(256) void reduce_k(const float* __restrict__ bias,
                                                float* __restrict__ out)
{
    int i = blockIdx.x*256 + threadIdx.x;
    if (i >= BB*64*HW) return;
    int pix = i & (HW - 1);
    int c   = (i >> 14) & 63;
    int b   = i >> 20;
    float s = bias[c];
#pragma unroll
    for (int q = 0; q < 4; q++)
        s += g_part[(((size_t)(q*BB + b))*64 + c)*HW + pix];
    out[i] = s;
}

// ==================== launch ====================
extern "C" void kernel_launch(void* const* d_in, const int* in_sizes, int n_in,
                              void* d_out, int out_size)
{
    const float* x   = (const float*)d_in[0];
    const float* exf = (const float*)d_in[1];
    const float* f1  = (const float*)d_in[2];
    const float* f2  = (const float*)d_in[3];
    const float* w1  = (const float*)d_in[4];
    const float* b1  = (const float*)d_in[5];
    const float* w2  = (const float*)d_in[6];
    const float* b2  = (const float*)d_in[7];
    const float* w3  = (const float*)d_in[8];
    const float* b3  = (const float*)d_in[9];
    const float* w4  = (const float*)d_in[10];
    const float* b4  = (const float*)d_in[11];
    const float* dw  = (const float*)d_in[12];
    const float* db  = (const float*)d_in[13];
    float* out = (float*)d_out;

    uint32_t *p_in0, *p_h1, *p_h2, *p_h3;
    uint16_t *p_w1h, *p_w1l, *p_w2h, *p_w2l, *p_w3h, *p_w3l, *p_w4h, *p_w4l;
    cudaGetSymbolAddress((void**)&p_in0, g_in0);
    cudaGetSymbolAddress((void**)&p_h1,  g_h1);
    cudaGetSymbolAddress((void**)&p_h2,  g_h2);
    cudaGetSymbolAddress((void**)&p_h3,  g_h3);
    cudaGetSymbolAddress((void**)&p_w1h, g_w1h);  cudaGetSymbolAddress((void**)&p_w1l, g_w1l);
    cudaGetSymbolAddress((void**)&p_w2h, g_w2h);  cudaGetSymbolAddress((void**)&p_w2l, g_w2l);
    cudaGetSymbolAddress((void**)&p_w3h, g_w3h);  cudaGetSymbolAddress((void**)&p_w3l, g_w3l);
    cudaGetSymbolAddress((void**)&p_w4h, g_w4h);  cudaGetSymbolAddress((void**)&p_w4l, g_w4l);

    const int SMTOT = 112320 + 55296;   // 167616
    cudaFuncSetAttribute(convmma_k<196,64,64,0>,  cudaFuncAttributeMaxDynamicSharedMemorySize, SMTOT);
    cudaFuncSetAttribute(convmma_k<64,64,64,0>,   cudaFuncAttributeMaxDynamicSharedMemorySize, SMTOT);
    cudaFuncSetAttribute(convmma_k<64,448,432,1>, cudaFuncAttributeMaxDynamicSharedMemorySize, SMTOT);

    pack_in0_k<<<dim3(HW/64, 4, BB), 256>>>(exf, f1, f2);
    transp_x_k<<<dim3(HW/256, 16, BB), 256>>>(x);
    transp_w_k<<<(16*72*64 + 255)/256, 256>>>(dw);
    wprep_k<<<(36*64*72  + 255)/256, 256>>>(w1, 196, 64, 64, 36, p_w1h, p_w1l);
    wprep_k<<<(9*64*72   + 255)/256, 256>>>(w2,  64, 64, 64,  9, p_w2h, p_w2l);
    wprep_k<<<(9*64*72   + 255)/256, 256>>>(w3,  64, 64, 64,  9, p_w3h, p_w3l);
    wprep_k<<<(9*448*72  + 255)/256, 256>>>(w4,  64, 432, 448, 9, p_w4h, p_w4l);

    convmma_k<196,64,64,0> <<<dim3(BB*128, 1), 512, SMTOT>>>(p_in0, p_w1h, p_w1l, b1, p_h1, nullptr, nullptr);
    convmma_k<64,64,64,0>  <<<dim3(BB*128, 1), 512, SMTOT>>>(p_h1,  p_w2h, p_w2l, b2, p_h2, nullptr, nullptr);
    convmma_k<64,64,64,0>  <<<dim3(BB*128, 1), 512, SMTOT>>>(p_h2,  p_w3h, p_w3l, b3, p_h3, nullptr, nullptr);
    convmma_k<64,448,432,1><<<dim3(BB*128, 7), 512, SMTOT>>>(p_h3,  p_w4h, p_w4l, b4, nullptr, f1, f2);

    dcn4_k<<<dim3(256, BB, 4), 256>>>();
    reduce_k<<<(BB*64*HW + 255)/256, 256>>>(db, out);
}

// round 10
// speedup vs baseline: 1.1049x; 1.1049x over previous
#include <cuda_runtime.h>
#include <cuda_bf16.h>
#include <cuda_fp16.h>
#include <math.h>
#include <stdint.h>

#define HH 128
#define WW 128
#define HW 16384
#define BB 2

// ==================== helpers ====================
__device__ __forceinline__ uint32_t smem_u32(const void* p) {
    uint32_t a;
    asm("{ .reg .u64 t; cvta.to.shared.u64 t, %1; cvt.u32.u64 %0, t; }" : "=r"(a) : "l"(p));
    return a;
}
__device__ __forceinline__ void ldsm_x4(uint32_t* r, uint32_t addr) {
    asm volatile("ldmatrix.sync.aligned.m8n8.x4.shared.b16 {%0,%1,%2,%3}, [%4];"
        : "=r"(r[0]), "=r"(r[1]), "=r"(r[2]), "=r"(r[3]) : "r"(addr));
}
__device__ __forceinline__ void mma_bf16(float* c, const uint32_t* a, const uint32_t* b) {
    asm volatile(
        "mma.sync.aligned.m16n8k16.row.col.f32.bf16.bf16.f32 "
        "{%0,%1,%2,%3}, {%4,%5,%6,%7}, {%8,%9}, {%0,%1,%2,%3};"
        : "+f"(c[0]), "+f"(c[1]), "+f"(c[2]), "+f"(c[3])
        : "r"(a[0]), "r"(a[1]), "r"(a[2]), "r"(a[3]), "r"(b[0]), "r"(b[1]));
}
__device__ __forceinline__ uint32_t pack_bf(float v) {
    __nv_bfloat16 h = __float2bfloat16(v);
    float hf = __bfloat162float(h);
    __nv_bfloat16 l = __float2bfloat16(v - hf);
    return (uint32_t)__bfloat16_as_ushort(h) | ((uint32_t)__bfloat16_as_ushort(l) << 16);
}
#define CP_ASYNC16(dst, src, sz) \
    asm volatile("cp.async.cg.shared.global [%0], [%1], 16, %2;" \
        :: "r"(dst), "l"(src), "r"(sz))
#define CP_COMMIT()  asm volatile("cp.async.commit_group;" ::: "memory")
#define CP_WAIT0()   asm volatile("cp.async.wait_group 0;" ::: "memory")

// ==================== scratch globals ====================
// activations channels-last, SPLIT bf16 planes: [b][cc][pix][64]
__device__ __align__(16) uint16_t g_in0h[BB*4*HW*64], g_in0l[BB*4*HW*64];
__device__ __align__(16) uint16_t g_h1h [BB*HW*64],   g_h1l [BB*HW*64];
__device__ __align__(16) uint16_t g_h2h [BB*HW*64],   g_h2l [BB*HW*64];
__device__ __align__(16) uint16_t g_h3h [BB*HW*64],   g_h3l [BB*HW*64];
__device__ float4   g_offm[BB*144*HW];    // {oy, ox, mask, pad}
__device__ __half   g_xt  [BB*128*HW];    // x fp16 channels-last [b][g][pix][8]
__device__ float    g_wt  [16*72*64];
__device__ float    g_part[4*BB*64*HW];
// weight tiles: [j][CoutP rows][72 cols] bf16, zero-padded
__device__ __align__(16) uint16_t g_w1h[36*64*72],  g_w1l[36*64*72];
__device__ __align__(16) uint16_t g_w2h[9*64*72],   g_w2l[9*64*72];
__device__ __align__(16) uint16_t g_w3h[9*64*72],   g_w3l[9*64*72];
__device__ __align__(16) uint16_t g_w4h[9*448*72],  g_w4l[9*448*72];

// ==================== prep kernels ====================
__global__ __launch_bounds__(256) void pack_in0_k(
    const float* __restrict__ ef, const float* __restrict__ f1, const float* __restrict__ f2)
{
    __shared__ uint32_t S[64*65];
    int cc = blockIdx.y, b = blockIdx.z;
    int pix0 = blockIdx.x * 64;
    int t = threadIdx.x;
    for (int i = t; i < 4096; i += 256) {
        int ch = i >> 6, px = i & 63;
        int g = cc*64 + ch;
        float v = 0.f;
        if (g < 192)      v = ef[((size_t)b*192 + g)*HW + pix0 + px];
        else if (g < 194) v = f1[((size_t)b*2 + (g-192))*HW + pix0 + px];
        else if (g < 196) v = f2[((size_t)b*2 + (g-194))*HW + pix0 + px];
        S[ch*65 + px] = pack_bf(v);
    }
    __syncthreads();
    for (int i = t; i < 2048; i += 256) {
        int px = i >> 5, c2 = i & 31;
        uint32_t u0 = S[(c2*2)*65 + px];
        uint32_t u1 = S[(c2*2+1)*65 + px];
        size_t base = ((((size_t)b*4 + cc)*HW + pix0 + px) << 6) >> 1;  // uint32 index
        ((uint32_t*)g_in0h)[base + c2] = (u0 & 0xffffu) | (u1 << 16);
        ((uint32_t*)g_in0l)[base + c2] = (u0 >> 16) | (u1 & 0xffff0000u);
    }
}

__global__ __launch_bounds__(256) void wprep_k(
    const float* __restrict__ w, int Cin, int CoutR, int CoutP, int J,
    uint16_t* __restrict__ dh, uint16_t* __restrict__ dl)
{
    int idx = blockIdx.x*256 + threadIdx.x;
    if (idx >= J*CoutP*72) return;
    int col = idx % 72;
    int o   = (idx / 72) % CoutP;
    int j   = idx / (72*CoutP);
    int cc = j / 9, kk = j % 9;
    int cin = cc*64 + col;
    float v = (col < 64 && cin < Cin && o < CoutR) ? w[((size_t)o*Cin + cin)*9 + kk] : 0.f;
    __nv_bfloat16 h = __float2bfloat16(v);
    float hf = __bfloat162float(h);
    __nv_bfloat16 l = __float2bfloat16(v - hf);
    dh[idx] = __bfloat16_as_ushort(h);
    dl[idx] = __bfloat16_as_ushort(l);
}

__global__ __launch_bounds__(256) void transp_x_k(const float* __restrict__ x)
{
    __shared__ float S[8*257];
    int g = blockIdx.y, b = blockIdx.z;
    int pix0 = blockIdx.x * 256;
    int t = threadIdx.x;
    for (int i = t; i < 2048; i += 256) {
        int ch = i >> 8, px = i & 255;
        S[ch*257 + px] = x[((size_t)(b*128 + g*8 + ch))*HW + pix0 + px];
    }
    __syncthreads();
    for (int i = t; i < 2048; i += 256) {
        int px = i >> 3, ch = i & 7;
        g_xt[(((size_t)(b*16 + g))*HW + pix0 + px)*8 + ch] = __float2half(S[ch*257 + px]);
    }
}

__global__ __launch_bounds__(256) void transp_w_k(const float* __restrict__ w)
{
    int i = blockIdx.x*256 + threadIdx.x;
    if (i >= 16*72*64) return;
    int o = i & 63, j = (i >> 6) % 72, g = i / (72*64);
    g_wt[i] = w[(size_t)o*1152 + (g*8 + j/9)*9 + (j % 9)];
}

// ==================== mma.sync conv3x3 (split planes + cp.async) ====================
// CTA = (b, y, half-row): M=64 px, N=64 cout chunk (blockIdx.y), 256 thr, 8 warps (4Mx2N).
// RT: 3 halo rows x 66 px x 64ch, hi/lo planes, stride 144B; A for (ky,kx) = RT[ky][m+kx].
// 3-term bf16 split: D = Ah*Bh + Ah*Bl + Al*Bh, fp32 accumulate.
template<int CIN, int COUTP, int COUTR, int EPI>
__global__ __launch_bounds__(256) void convmma_k(
    const uint16_t* __restrict__ inh, const uint16_t* __restrict__ inl,
    const uint16_t* __restrict__ wh,  const uint16_t* __restrict__ wl,
    const float* __restrict__ bias,
    uint16_t* __restrict__ outh, uint16_t* __restrict__ outl,
    const float* __restrict__ flow1, const float* __restrict__ flow2)
{
    extern __shared__ char sm[];
    constexpr int CCH = (CIN + 63) / 64;
    const int OFF_RTH = 0;           // 3*66*144 = 28512
    const int OFF_RTL = 28512;
    const int OFF_B   = 57024;       // 3 kx * (hi 9216 + lo 9216) = 55296

    uint32_t sbase = smem_u32(sm);
    int t = threadIdx.x, lane = t & 31, wid = t >> 5;
    int bx = blockIdx.x;
    int b = bx >> 8;
    int idx = bx & 255;
    int y = idx >> 1, x0 = (idx & 1) * 64;
    int nc = blockIdx.y;
    int warp_m = wid & 3, warp_n = wid >> 2;

    float acc[4][4];
#pragma unroll
    for (int i = 0; i < 4; i++)
#pragma unroll
        for (int j2 = 0; j2 < 4; j2++) acc[i][j2] = 0.f;

    const uint32_t aH_row = sbase + OFF_RTH + (uint32_t)(warp_m*16 + (lane & 15))*144u;
    const uint32_t aL_row = sbase + OFF_RTL + (uint32_t)(warp_m*16 + (lane & 15))*144u;
    const int aseg = lane >> 4;
    const uint32_t brq = (uint32_t)(warp_n*32 + (lane & 7) + ((lane >> 4) & 1)*8)*144u;
    const int bseg = (lane >> 3) & 1;

    for (int cc = 0; cc < CCH; cc++) {
        __syncthreads();   // prev cc's ldsm done before RT overwrite
        // issue RT cp.async: 2 planes x 3 rows x 66 px x 8 chunks = 3168
        {
            size_t imgoff = ((size_t)b*CCH + cc)*HW;
            for (int i = t; i < 3168; i += 256) {
                int f = i & 7;
                int rest = i >> 3;
                int p = rest % 66;
                int rest2 = rest / 66;
                int ry = rest2 % 3;
                int plane = rest2 / 3;
                int r = y + ry - 1, x = x0 + p - 1;
                uint32_t ok = ((unsigned)r < (unsigned)HH && (unsigned)x < (unsigned)WW) ? 16u : 0u;
                int rc = min(max(r, 0), HH-1), xc = min(max(x, 0), WW-1);
                const uint16_t* src = (plane ? inl : inh) + ((imgoff + (size_t)rc*WW + xc) << 6) + (f << 3);
                uint32_t dst = sbase + (plane ? OFF_RTL : OFF_RTH) + (ry*66 + p)*144 + f*16;
                CP_ASYNC16(dst, src, ok);
            }
            CP_COMMIT();
        }
        for (int ky = 0; ky < 3; ky++) {
            int r = y + ky - 1;
            if ((unsigned)r >= (unsigned)HH) continue;   // uniform skip
            __syncthreads();   // prev ky's ldsm done before B overwrite
            // issue B cp.async: 3 kx x 2 planes x 576 chunks = 3456
            {
                int j0 = cc*9 + ky*3;
                for (int i = t; i < 3456; i += 256) {
                    int c = i % 576;
                    int rest = i / 576;
                    int plane = rest & 1, kx = rest >> 1;
                    int o = c / 9, f = c % 9;
                    const uint16_t* src = (plane ? wl : wh)
                        + ((size_t)(j0 + kx)*COUTP + nc*64 + o)*72 + f*8;
                    uint32_t dst = sbase + OFF_B + (kx*2 + plane)*9216 + o*144 + f*16;
                    CP_ASYNC16(dst, src, 16u);
                }
                CP_COMMIT();
            }
            CP_WAIT0();
            __syncthreads();

            uint32_t rtH = aH_row + ky*66*144;
            uint32_t rtL = aL_row + ky*66*144;
#pragma unroll
            for (int kx = 0; kx < 3; kx++) {
                uint32_t aH0 = rtH + (uint32_t)kx*144u;
                uint32_t aL0 = rtL + (uint32_t)kx*144u;
                uint32_t bH  = sbase + OFF_B + kx*18432 + brq;
                uint32_t bL  = bH + 9216;
#pragma unroll
                for (int ks = 0; ks < 4; ks++) {
                    uint32_t ka = (uint32_t)(ks*16 + aseg*8)*2;
                    uint32_t kb = (uint32_t)(ks*16 + bseg*8)*2;
                    uint32_t a_h[4], a_l[4], b_h[2][4], b_l[2][4];
                    ldsm_x4(a_h, aH0 + ka);
                    ldsm_x4(a_l, aL0 + ka);
                    ldsm_x4(b_h[0], bH + kb);
                    ldsm_x4(b_h[1], bH + 16*144 + kb);
                    ldsm_x4(b_l[0], bL + kb);
                    ldsm_x4(b_l[1], bL + 16*144 + kb);
#pragma unroll
                    for (int np = 0; np < 2; np++)
#pragma unroll
                        for (int sub = 0; sub < 2; sub++) {
                            int nt = np*2 + sub;
                            mma_bf16(acc[nt], a_h, &b_h[np][sub*2]);
                            mma_bf16(acc[nt], a_h, &b_l[np][sub*2]);
                            mma_bf16(acc[nt], a_l, &b_h[np][sub*2]);
                        }
                }
            }
        }
    }

    int g = lane >> 2, tq = lane & 3;
    if (EPI == 0) {
        __syncthreads();    // all ldsm done before smem reuse
        uint32_t* OTH = (uint32_t*)sm;            // [64 px][36] packed hi pairs
        uint32_t* OTL = (uint32_t*)(sm + 9216);   // [64 px][36] packed lo pairs
#pragma unroll
        for (int nt = 0; nt < 4; nt++) {
            int cbase = warp_n*32 + nt*8 + tq*2;
            int c2 = cbase >> 1;
            float bv0 = bias[cbase], bv1 = bias[cbase + 1];
#pragma unroll
            for (int half = 0; half < 2; half++) {
                int px = warp_m*16 + g + half*8;
                float v0 = acc[nt][half*2]     + bv0;
                float v1 = acc[nt][half*2 + 1] + bv1;
                v0 = v0 >= 0.f ? v0 : 0.1f*v0;
                v1 = v1 >= 0.f ? v1 : 0.1f*v1;
                uint32_t u0 = pack_bf(v0), u1 = pack_bf(v1);
                OTH[px*36 + c2] = (u0 & 0xffffu) | (u1 << 16);
                OTL[px*36 + c2] = (u0 >> 16) | (u1 & 0xffff0000u);
            }
        }
        __syncthreads();
        for (int i = t; i < 512; i += 256) {
            int p = i >> 3, f = i & 7;
            size_t go = (((size_t)b*HW + y*WW + x0 + p) << 6) + (f << 3);
            *(float4*)(outh + go) = *(const float4*)((char*)OTH + p*144 + f*16);
            *(float4*)(outl + go) = *(const float4*)((char*)OTL + p*144 + f*16);
        }
    } else {
        float* dst = (float*)g_offm;
#pragma unroll
        for (int nt = 0; nt < 4; nt++)
#pragma unroll
            for (int rg = 0; rg < 4; rg++) {
                int px = warp_m*16 + g + ((rg >> 1) ? 8 : 0);
                int c  = nc*64 + warp_n*32 + nt*8 + tq*2 + (rg & 1);
                if (c >= COUTR) continue;
                int pix = y*WW + x0 + px;
                float v = acc[nt][rg] + bias[c];
                if (c < 288) {
                    int ch = c >> 1, comp = c & 1;
                    const float* fl = (c < 144) ? flow1 : flow2;
                    float add = fl[((size_t)b*2 + (1 - comp))*HW + pix];
                    dst[(((size_t)b*144 + ch)*HW + pix)*4 + comp] = 10.f*tanhf(v) + add;
                } else {
                    int ch = c - 288;
                    dst[(((size_t)b*144 + ch)*HW + pix)*4 + 2] = 1.f/(1.f + expf(-v));
                }
            }
    }
}

// ==================== modulated deformable conv (fp16 gather, fp32 GEMM) ====================
__global__ __launch_bounds__(256) void dcn4_k()
{
    __shared__ float s_val[72][64];
    __shared__ float s_w[72][64];
    int p0 = blockIdx.x << 6, b = blockIdx.y, q = blockIdx.z;
    int t = threadIdx.x;
    int o4 = (t & 15) << 2, pb = (t >> 4) << 2;
    float accs[16];
#pragma unroll
    for (int i = 0; i < 16; i++) accs[i] = 0.f;
    const float4* offm = g_offm + (size_t)b*144*HW;

    for (int gi = 0; gi < 4; gi++) {
        int g = q*4 + gi;
        {
            const float4* src = (const float4*)(g_wt + (size_t)g*4608);
            float4* dstw = (float4*)&s_w[0][0];
            for (int i = t; i < 1152; i += 256) dstw[i] = src[i];
        }
        const __half* gb = g_xt + ((size_t)(b*16 + g))*HW*8;
#pragma unroll
        for (int rep = 0; rep < 3; rep++) {
            int task = t + (rep << 8);
            if (task < 576) {
                int k = task >> 6, p = task & 63;
                int pix = p0 + p, y = pix >> 7, x = pix & 127;
                int ch = g*9 + k;
                float4 om = offm[(size_t)ch*HW + pix];
                float m = om.z;
                float py = (float)(y + (k/3) - 1) + om.x;
                float px = (float)(x + (k%3) - 1) + om.y;
                float fy = floorf(py), fx = floorf(px);
                float wy = py - fy, wx = px - fx;
                int y0 = (int)fy, x0 = (int)fx, y1 = y0 + 1, x1 = x0 + 1;
                float vy0 = ((unsigned)y0 < HH) ? 1.f : 0.f;
                float vy1 = ((unsigned)y1 < HH) ? 1.f : 0.f;
                float vx0 = ((unsigned)x0 < WW) ? 1.f : 0.f;
                float vx1 = ((unsigned)x1 < WW) ? 1.f : 0.f;
                int y0c = min(max(y0,0),HH-1), y1c = min(max(y1,0),HH-1);
                int x0c = min(max(x0,0),WW-1), x1c = min(max(x1,0),WW-1);
                float w00 = (1.f-wy)*(1.f-wx)*m*vy0*vx0;
                float w01 = (1.f-wy)*wx      *m*vy0*vx1;
                float w10 = wy*(1.f-wx)      *m*vy1*vx0;
                float w11 = wy*wx            *m*vy1*vx1;
                float v[8];
                uint4 r00 = *(const uint4*)(gb + ((size_t)(y0c*WW + x0c) << 3));
                uint4 r01 = *(const uint4*)(gb + ((size_t)(y0c*WW + x1c) << 3));
                uint4 r10 = *(const uint4*)(gb + ((size_t)(y1c*WW + x0c) << 3));
                uint4 r11 = *(const uint4*)(gb + ((size_t)(y1c*WW + x1c) << 3));
                const __half2* h00 = (const __half2*)&r00;
                const __half2* h01 = (const __half2*)&r01;
                const __half2* h10 = (const __half2*)&r10;
                const __half2* h11 = (const __half2*)&r11;
#pragma unroll
                for (int i = 0; i < 4; i++) {
                    float2 f00 = __half22float2(h00[i]);
                    float2 f01 = __half22float2(h01[i]);
                    float2 f10 = __half22float2(h10[i]);
                    float2 f11 = __half22float2(h11[i]);
                    v[i*2]   = w00*f00.x + w01*f01.x + w10*f10.x + w11*f11.x;
                    v[i*2+1] = w00*f00.y + w01*f01.y + w10*f10.y + w11*f11.y;
                }
#pragma unroll
                for (int c = 0; c < 8; c++) s_val[c*9 + k][p] = v[c];
            }
        }
        __syncthreads();

#pragma unroll 8
        for (int j = 0; j < 72; j++) {
            float4 wv = *(const float4*)&s_w[j][o4];
            float4 vv = *(const float4*)&s_val[j][pb];
            accs[0]  = fmaf(wv.x, vv.x, accs[0]);
            accs[1]  = fmaf(wv.x, vv.y, accs[1]);
            accs[2]  = fmaf(wv.x, vv.z, accs[2]);
            accs[3]  = fmaf(wv.x, vv.w, accs[3]);
            accs[4]  = fmaf(wv.y, vv.x, accs[4]);
            accs[5]  = fmaf(wv.y, vv.y, accs[5]);
            accs[6]  = fmaf(wv.y, vv.z, accs[6]);
            accs[7]  = fmaf(wv.y, vv.w, accs[7]);
            accs[8]  = fmaf(wv.z, vv.x, accs[8]);
            accs[9]  = fmaf(wv.z, vv.y, accs[9]);
            accs[10] = fmaf(wv.z, vv.z, accs[10]);
            accs[11] = fmaf(wv.z, vv.w, accs[11]);
            accs[12] = fmaf(wv.w, vv.x, accs[12]);
            accs[13] = fmaf(wv.w, vv.y, accs[13]);
            accs[14] = fmaf(wv.w, vv.z, accs[14]);
            accs[15] = fmaf(wv.w, vv.w, accs[15]);
        }
        __syncthreads();
    }

    float* pout = g_part + (((size_t)(q*BB + b))*64)*HW;
#pragma unroll
    for (int oi = 0; oi < 4; oi++)
#pragma unroll
        for (int pi = 0; pi < 4; pi++)
            pout[(size_t)(o4 + oi)*HW + p0 + pb + pi] = accs[oi*4 + pi];
}

__global__ __launch_bounds__(256) void reduce_k(const float* __restrict__ bias,
                                                float* __restrict__ out)
{
    int i = blockIdx.x*256 + threadIdx.x;
    if (i >= BB*64*HW) return;
    int pix = i & (HW - 1);
    int c   = (i >> 14) & 63;
    int b   = i >> 20;
    float s = bias[c];
#pragma unroll
    for (int q = 0; q < 4; q++)
        s += g_part[(((size_t)(q*BB + b))*64 + c)*HW + pix];
    out[i] = s;
}

// ==================== launch ====================
extern "C" void kernel_launch(void* const* d_in, const int* in_sizes, int n_in,
                              void* d_out, int out_size)
{
    const float* x   = (const float*)d_in[0];
    const float* exf = (const float*)d_in[1];
    const float* f1  = (const float*)d_in[2];
    const float* f2  = (const float*)d_in[3];
    const float* w1  = (const float*)d_in[4];
    const float* b1  = (const float*)d_in[5];
    const float* w2  = (const float*)d_in[6];
    const float* b2  = (const float*)d_in[7];
    const float* w3  = (const float*)d_in[8];
    const float* b3  = (const float*)d_in[9];
    const float* w4  = (const float*)d_in[10];
    const float* b4  = (const float*)d_in[11];
    const float* dw  = (const float*)d_in[12];
    const float* db  = (const float*)d_in[13];
    float* out = (float*)d_out;

    uint16_t *p_i0h, *p_i0l, *p_h1h, *p_h1l, *p_h2h, *p_h2l, *p_h3h, *p_h3l;
    uint16_t *p_w1h, *p_w1l, *p_w2h, *p_w2l, *p_w3h, *p_w3l, *p_w4h, *p_w4l;
    cudaGetSymbolAddress((void**)&p_i0h, g_in0h); cudaGetSymbolAddress((void**)&p_i0l, g_in0l);
    cudaGetSymbolAddress((void**)&p_h1h, g_h1h);  cudaGetSymbolAddress((void**)&p_h1l, g_h1l);
    cudaGetSymbolAddress((void**)&p_h2h, g_h2h);  cudaGetSymbolAddress((void**)&p_h2l, g_h2l);
    cudaGetSymbolAddress((void**)&p_h3h, g_h3h);  cudaGetSymbolAddress((void**)&p_h3l, g_h3l);
    cudaGetSymbolAddress((void**)&p_w1h, g_w1h);  cudaGetSymbolAddress((void**)&p_w1l, g_w1l);
    cudaGetSymbolAddress((void**)&p_w2h, g_w2h);  cudaGetSymbolAddress((void**)&p_w2l, g_w2l);
    cudaGetSymbolAddress((void**)&p_w3h, g_w3h);  cudaGetSymbolAddress((void**)&p_w3l, g_w3l);
    cudaGetSymbolAddress((void**)&p_w4h, g_w4h);  cudaGetSymbolAddress((void**)&p_w4l, g_w4l);

    const int SMTOT = 57024 + 55296;   // 112320
    cudaFuncSetAttribute(convmma_k<196,64,64,0>,  cudaFuncAttributeMaxDynamicSharedMemorySize, SMTOT);
    cudaFuncSetAttribute(convmma_k<64,64,64,0>,   cudaFuncAttributeMaxDynamicSharedMemorySize, SMTOT);
    cudaFuncSetAttribute(convmma_k<64,448,432,1>, cudaFuncAttributeMaxDynamicSharedMemorySize, SMTOT);

    pack_in0_k<<<dim3(HW/64, 4, BB), 256>>>(exf, f1, f2);
    transp_x_k<<<dim3(HW/256, 16, BB), 256>>>(x);
    transp_w_k<<<(16*72*64 + 255)/256, 256>>>(dw);
    wprep_k<<<(36*64*72  + 255)/256, 256>>>(w1, 196, 64, 64, 36, p_w1h, p_w1l);
    wprep_k<<<(9*64*72   + 255)/256, 256>>>(w2,  64, 64, 64,  9, p_w2h, p_w2l);
    wprep_k<<<(9*64*72   + 255)/256, 256>>>(w3,  64, 64, 64,  9, p_w3h, p_w3l);
    wprep_k<<<(9*448*72  + 255)/256, 256>>>(w4,  64, 432, 448, 9, p_w4h, p_w4l);

    convmma_k<196,64,64,0> <<<dim3(BB*256, 1), 256, SMTOT>>>(p_i0h, p_i0l, p_w1h, p_w1l, b1, p_h1h, p_h1l, nullptr, nullptr);
    convmma_k<64,64,64,0>  <<<dim3(BB*256, 1), 256, SMTOT>>>(p_h1h, p_h1l, p_w2h, p_w2l, b2, p_h2h, p_h2l, nullptr, nullptr);
    convmma_k<64,64,64,0>  <<<dim3(BB*256, 1), 256, SMTOT>>>(p_h2h, p_h2l, p_w3h, p_w3l, b3, p_h3h, p_h3l, nullptr, nullptr);
    convmma_k<64,448,432,1><<<dim3(BB*256, 7), 256, SMTOT>>>(p_h3h, p_h3l, p_w4h, p_w4l, b4, nullptr, nullptr, f1, f2);

    dcn4_k<<<dim3(256, BB, 4), 256>>>();
    reduce_k<<<(BB*64*HW + 255)/256, 256>>>(db, out);
}

// round 12
// speedup vs baseline: 1.3071x; 1.1830x over previous
#include <cuda_runtime.h>
#include <cuda_bf16.h>
#include <cuda_fp16.h>
#include <math.h>
#include <stdint.h>

#define HH 128
#define WW 128
#define HW 16384
#define BB 2

// ==================== helpers ====================
__device__ __forceinline__ uint32_t smem_u32(const void* p) {
    uint32_t a;
    asm("{ .reg .u64 t; cvta.to.shared.u64 t, %1; cvt.u32.u64 %0, t; }" : "=r"(a) : "l"(p));
    return a;
}
__device__ __forceinline__ void ldsm_x4(uint32_t* r, uint32_t addr) {
    asm volatile("ldmatrix.sync.aligned.m8n8.x4.shared.b16 {%0,%1,%2,%3}, [%4];"
        : "=r"(r[0]), "=r"(r[1]), "=r"(r[2]), "=r"(r[3]) : "r"(addr));
}
__device__ __forceinline__ void mma_bf16(float* c, const uint32_t* a, const uint32_t* b) {
    asm volatile(
        "mma.sync.aligned.m16n8k16.row.col.f32.bf16.bf16.f32 "
        "{%0,%1,%2,%3}, {%4,%5,%6,%7}, {%8,%9}, {%0,%1,%2,%3};"
        : "+f"(c[0]), "+f"(c[1]), "+f"(c[2]), "+f"(c[3])
        : "r"(a[0]), "r"(a[1]), "r"(a[2]), "r"(a[3]), "r"(b[0]), "r"(b[1]));
}
__device__ __forceinline__ void mma_f16(float* c, const uint32_t* a, const uint32_t* b) {
    asm volatile(
        "mma.sync.aligned.m16n8k16.row.col.f32.f16.f16.f32 "
        "{%0,%1,%2,%3}, {%4,%5,%6,%7}, {%8,%9}, {%0,%1,%2,%3};"
        : "+f"(c[0]), "+f"(c[1]), "+f"(c[2]), "+f"(c[3])
        : "r"(a[0]), "r"(a[1]), "r"(a[2]), "r"(a[3]), "r"(b[0]), "r"(b[1]));
}
__device__ __forceinline__ uint32_t pack_bf(float v) {
    __nv_bfloat16 h = __float2bfloat16(v);
    float hf = __bfloat162float(h);
    __nv_bfloat16 l = __float2bfloat16(v - hf);
    return (uint32_t)__bfloat16_as_ushort(h) | ((uint32_t)__bfloat16_as_ushort(l) << 16);
}
#define CP_ASYNC16(dst, src, sz) \
    asm volatile("cp.async.cg.shared.global [%0], [%1], 16, %2;" \
        :: "r"(dst), "l"(src), "r"(sz))
#define CP_COMMIT()  asm volatile("cp.async.commit_group;" ::: "memory")
#define CP_WAIT0()   asm volatile("cp.async.wait_group 0;" ::: "memory")

// ==================== scratch globals ====================
__device__ __align__(16) uint16_t g_in0h[BB*4*HW*64], g_in0l[BB*4*HW*64];
__device__ __align__(16) uint16_t g_h1h [BB*HW*64],   g_h1l [BB*HW*64];
__device__ __align__(16) uint16_t g_h2h [BB*HW*64],   g_h2l [BB*HW*64];
__device__ __align__(16) uint16_t g_h3h [BB*HW*64],   g_h3l [BB*HW*64];
__device__ float4   g_offm[BB*144*HW];    // {oy, ox, mask, pad}
__device__ __align__(16) __half g_xt[BB*128*HW];  // x fp16 channels-last [b][g][pix][8]
__device__ float    g_part[4*BB*64*HW];
// dcn weights fp16 2-plane, mma layout [g][o][88], j=k*8+c, 72..87 zero
__device__ __align__(16) __half g_wth[16*64*88], g_wtl[16*64*88];
// conv weight tiles: [j][CoutP rows][72 cols] bf16, zero-padded
__device__ __align__(16) uint16_t g_w1h[36*64*72],  g_w1l[36*64*72];
__device__ __align__(16) uint16_t g_w2h[9*64*72],   g_w2l[9*64*72];
__device__ __align__(16) uint16_t g_w3h[9*64*72],   g_w3l[9*64*72];
__device__ __align__(16) uint16_t g_w4h[9*448*72],  g_w4l[9*448*72];

// ==================== prep kernels ====================
__global__ __launch_bounds__(256) void pack_in0_k(
    const float* __restrict__ ef, const float* __restrict__ f1, const float* __restrict__ f2)
{
    __shared__ uint32_t S[64*65];
    int cc = blockIdx.y, b = blockIdx.z;
    int pix0 = blockIdx.x * 64;
    int t = threadIdx.x;
    for (int i = t; i < 4096; i += 256) {
        int ch = i >> 6, px = i & 63;
        int g = cc*64 + ch;
        float v = 0.f;
        if (g < 192)      v = ef[((size_t)b*192 + g)*HW + pix0 + px];
        else if (g < 194) v = f1[((size_t)b*2 + (g-192))*HW + pix0 + px];
        else if (g < 196) v = f2[((size_t)b*2 + (g-194))*HW + pix0 + px];
        S[ch*65 + px] = pack_bf(v);
    }
    __syncthreads();
    for (int i = t; i < 2048; i += 256) {
        int px = i >> 5, c2 = i & 31;
        uint32_t u0 = S[(c2*2)*65 + px];
        uint32_t u1 = S[(c2*2+1)*65 + px];
        size_t base = ((((size_t)b*4 + cc)*HW + pix0 + px) << 6) >> 1;
        ((uint32_t*)g_in0h)[base + c2] = (u0 & 0xffffu) | (u1 << 16);
        ((uint32_t*)g_in0l)[base + c2] = (u0 >> 16) | (u1 & 0xffff0000u);
    }
}

__global__ __launch_bounds__(256) void wprep_k(
    const float* __restrict__ w, int Cin, int CoutR, int CoutP, int J,
    uint16_t* __restrict__ dh, uint16_t* __restrict__ dl)
{
    int idx = blockIdx.x*256 + threadIdx.x;
    if (idx >= J*CoutP*72) return;
    int col = idx % 72;
    int o   = (idx / 72) % CoutP;
    int j   = idx / (72*CoutP);
    int cc = j / 9, kk = j % 9;
    int cin = cc*64 + col;
    float v = (col < 64 && cin < Cin && o < CoutR) ? w[((size_t)o*Cin + cin)*9 + kk] : 0.f;
    __nv_bfloat16 h = __float2bfloat16(v);
    float hf = __bfloat162float(h);
    __nv_bfloat16 l = __float2bfloat16(v - hf);
    dh[idx] = __bfloat16_as_ushort(h);
    dl[idx] = __bfloat16_as_ushort(l);
}

__global__ __launch_bounds__(256) void transp_x_k(const float* __restrict__ x)
{
    __shared__ float S[8*257];
    int g = blockIdx.y, b = blockIdx.z;
    int pix0 = blockIdx.x * 256;
    int t = threadIdx.x;
    for (int i = t; i < 2048; i += 256) {
        int ch = i >> 8, px = i & 255;
        S[ch*257 + px] = x[((size_t)(b*128 + g*8 + ch))*HW + pix0 + px];
    }
    __syncthreads();
    for (int i = t; i < 2048; i += 256) {
        int px = i >> 3, ch = i & 7;
        g_xt[(((size_t)(b*16 + g))*HW + pix0 + px)*8 + ch] = __float2half(S[ch*257 + px]);
    }
}

// dcn weights -> fp16 hi/lo planes, [g][o][88], j=k*8+c
__global__ __launch_bounds__(256) void wdcn_k(const float* __restrict__ w)
{
    int i = blockIdx.x*256 + threadIdx.x;
    if (i >= 16*64*88) return;
    int j = i % 88;
    int o = (i / 88) % 64;
    int g = i / (88*64);
    float v = 0.f;
    if (j < 72) {
        int k = j >> 3, c = j & 7;
        v = w[(size_t)o*1152 + (g*8 + c)*9 + k];
    }
    __half h = __float2half(v);
    __half l = __float2half(v - __half2float(h));
    g_wth[i] = h;
    g_wtl[i] = l;
}

// ==================== mma.sync conv3x3 (unchanged from R10 best) ====================
template<int CIN, int COUTP, int COUTR, int EPI>
__global__ __launch_bounds__(256) void convmma_k(
    const uint16_t* __restrict__ inh, const uint16_t* __restrict__ inl,
    const uint16_t* __restrict__ wh,  const uint16_t* __restrict__ wl,
    const float* __restrict__ bias,
    uint16_t* __restrict__ outh, uint16_t* __restrict__ outl,
    const float* __restrict__ flow1, const float* __restrict__ flow2)
{
    extern __shared__ char sm[];
    constexpr int CCH = (CIN + 63) / 64;
    const int OFF_RTH = 0;
    const int OFF_RTL = 28512;
    const int OFF_B   = 57024;

    uint32_t sbase = smem_u32(sm);
    int t = threadIdx.x, lane = t & 31, wid = t >> 5;
    int bx = blockIdx.x;
    int b = bx >> 8;
    int idx = bx & 255;
    int y = idx >> 1, x0 = (idx & 1) * 64;
    int nc = blockIdx.y;
    int warp_m = wid & 3, warp_n = wid >> 2;

    float acc[4][4];
#pragma unroll
    for (int i = 0; i < 4; i++)
#pragma unroll
        for (int j2 = 0; j2 < 4; j2++) acc[i][j2] = 0.f;

    const uint32_t aH_row = sbase + OFF_RTH + (uint32_t)(warp_m*16 + (lane & 15))*144u;
    const uint32_t aL_row = sbase + OFF_RTL + (uint32_t)(warp_m*16 + (lane & 15))*144u;
    const int aseg = lane >> 4;
    const uint32_t brq = (uint32_t)(warp_n*32 + (lane & 7) + ((lane >> 4) & 1)*8)*144u;
    const int bseg = (lane >> 3) & 1;

    for (int cc = 0; cc < CCH; cc++) {
        __syncthreads();
        {
            size_t imgoff = ((size_t)b*CCH + cc)*HW;
            for (int i = t; i < 3168; i += 256) {
                int f = i & 7;
                int rest = i >> 3;
                int p = rest % 66;
                int rest2 = rest / 66;
                int ry = rest2 % 3;
                int plane = rest2 / 3;
                int r = y + ry - 1, x = x0 + p - 1;
                uint32_t ok = ((unsigned)r < (unsigned)HH && (unsigned)x < (unsigned)WW) ? 16u : 0u;
                int rc = min(max(r, 0), HH-1), xc = min(max(x, 0), WW-1);
                const uint16_t* src = (plane ? inl : inh) + ((imgoff + (size_t)rc*WW + xc) << 6) + (f << 3);
                uint32_t dst = sbase + (plane ? OFF_RTL : OFF_RTH) + (ry*66 + p)*144 + f*16;
                CP_ASYNC16(dst, src, ok);
            }
            CP_COMMIT();
        }
        for (int ky = 0; ky < 3; ky++) {
            int r = y + ky - 1;
            if ((unsigned)r >= (unsigned)HH) continue;
            __syncthreads();
            {
                int j0 = cc*9 + ky*3;
                for (int i = t; i < 3456; i += 256) {
                    int c = i % 576;
                    int rest = i / 576;
                    int plane = rest & 1, kx = rest >> 1;
                    int o = c / 9, f = c % 9;
                    const uint16_t* src = (plane ? wl : wh)
                        + ((size_t)(j0 + kx)*COUTP + nc*64 + o)*72 + f*8;
                    uint32_t dst = sbase + OFF_B + (kx*2 + plane)*9216 + o*144 + f*16;
                    CP_ASYNC16(dst, src, 16u);
                }
                CP_COMMIT();
            }
            CP_WAIT0();
            __syncthreads();

            uint32_t rtH = aH_row + ky*66*144;
            uint32_t rtL = aL_row + ky*66*144;
#pragma unroll
            for (int kx = 0; kx < 3; kx++) {
                uint32_t aH0 = rtH + (uint32_t)kx*144u;
                uint32_t aL0 = rtL + (uint32_t)kx*144u;
                uint32_t bH  = sbase + OFF_B + kx*18432 + brq;
                uint32_t bL  = bH + 9216;
#pragma unroll
                for (int ks = 0; ks < 4; ks++) {
                    uint32_t ka = (uint32_t)(ks*16 + aseg*8)*2;
                    uint32_t kb = (uint32_t)(ks*16 + bseg*8)*2;
                    uint32_t a_h[4], a_l[4], b_h[2][4], b_l[2][4];
                    ldsm_x4(a_h, aH0 + ka);
                    ldsm_x4(a_l, aL0 + ka);
                    ldsm_x4(b_h[0], bH + kb);
                    ldsm_x4(b_h[1], bH + 16*144 + kb);
                    ldsm_x4(b_l[0], bL + kb);
                    ldsm_x4(b_l[1], bL + 16*144 + kb);
#pragma unroll
                    for (int np = 0; np < 2; np++)
#pragma unroll
                        for (int sub = 0; sub < 2; sub++) {
                            int nt = np*2 + sub;
                            mma_bf16(acc[nt], a_h, &b_h[np][sub*2]);
                            mma_bf16(acc[nt], a_h, &b_l[np][sub*2]);
                            mma_bf16(acc[nt], a_l, &b_h[np][sub*2]);
                        }
                }
            }
        }
    }

    int g = lane >> 2, tq = lane & 3;
    if (EPI == 0) {
        __syncthreads();
        uint32_t* OTH = (uint32_t*)sm;
        uint32_t* OTL = (uint32_t*)(sm + 9216);
#pragma unroll
        for (int nt = 0; nt < 4; nt++) {
            int cbase = warp_n*32 + nt*8 + tq*2;
            int c2 = cbase >> 1;
            float bv0 = bias[cbase], bv1 = bias[cbase + 1];
#pragma unroll
            for (int half = 0; half < 2; half++) {
                int px = warp_m*16 + g + half*8;
                float v0 = acc[nt][half*2]     + bv0;
                float v1 = acc[nt][half*2 + 1] + bv1;
                v0 = v0 >= 0.f ? v0 : 0.1f*v0;
                v1 = v1 >= 0.f ? v1 : 0.1f*v1;
                uint32_t u0 = pack_bf(v0), u1 = pack_bf(v1);
                OTH[px*36 + c2] = (u0 & 0xffffu) | (u1 << 16);
                OTL[px*36 + c2] = (u0 >> 16) | (u1 & 0xffff0000u);
            }
        }
        __syncthreads();
        for (int i = t; i < 512; i += 256) {
            int p = i >> 3, f = i & 7;
            size_t go = (((size_t)b*HW + y*WW + x0 + p) << 6) + (f << 3);
            *(float4*)(outh + go) = *(const float4*)((char*)OTH + p*144 + f*16);
            *(float4*)(outl + go) = *(const float4*)((char*)OTL + p*144 + f*16);
        }
    } else {
        float* dst = (float*)g_offm;
#pragma unroll
        for (int nt = 0; nt < 4; nt++)
#pragma unroll
            for (int rg = 0; rg < 4; rg++) {
                int px = warp_m*16 + g + ((rg >> 1) ? 8 : 0);
                int c  = nc*64 + warp_n*32 + nt*8 + tq*2 + (rg & 1);
                if (c >= COUTR) continue;
                int pix = y*WW + x0 + px;
                float v = acc[nt][rg] + bias[c];
                if (c < 288) {
                    int ch = c >> 1, comp = c & 1;
                    const float* fl = (c < 144) ? flow1 : flow2;
                    float add = fl[((size_t)b*2 + (1 - comp))*HW + pix];
                    dst[(((size_t)b*144 + ch)*HW + pix)*4 + comp] = 10.f*tanhf(v) + add;
                } else {
                    int ch = c - 288;
                    dst[(((size_t)b*144 + ch)*HW + pix)*4 + 2] = 1.f/(1.f + expf(-v));
                }
            }
    }
}

// ==================== dcn: fp16 gather + tensor-core GEMM ====================
// Block: 256 thr, 64 px, 4 groups (quad q). s_valT [64 px][88 j] fp16, j=k*8+c.
__global__ __launch_bounds__(256) void dcn4_k()
{
    __shared__ __align__(16) __half s_valT[64*88];
    __shared__ __align__(16) __half s_wh[64*88];
    __shared__ __align__(16) __half s_wl[64*88];
    int p0 = blockIdx.x << 6, b = blockIdx.y, q = blockIdx.z;
    int t = threadIdx.x, lane = t & 31, wid = t >> 5;
    int warp_m = wid & 3, warp_n = wid >> 2;

    float acc[4][4];
#pragma unroll
    for (int i = 0; i < 4; i++)
#pragma unroll
        for (int j2 = 0; j2 < 4; j2++) acc[i][j2] = 0.f;

    // zero j-padding cols 72..87: 64 rows x 2 uint4 (byte off = p*176 + 144 + f*16)
    if (t < 128) {
        int p = t >> 1, f = t & 1;
        *(uint4*)(s_valT + p*88 + 72 + f*8) = make_uint4(0,0,0,0);
    }

    const float4* offm = g_offm + (size_t)b*144*HW;
    uint32_t sb_val = smem_u32(s_valT);
    uint32_t sb_wh  = smem_u32(s_wh);
    uint32_t sb_wl  = smem_u32(s_wl);

    const uint32_t aRow = (uint32_t)(warp_m*16 + (lane & 15))*176u + (uint32_t)((lane >> 4)*8)*2u;
    const uint32_t bRow = (uint32_t)(warp_n*32 + (lane & 7) + ((lane >> 4) & 1)*8)*176u
                        + (uint32_t)(((lane >> 3) & 1)*8)*2u;

    for (int gi = 0; gi < 4; gi++) {
        int g = q*4 + gi;
        __syncthreads();   // prior GEMM reads done
        // stage weights (coalesced uint4 copies)
        {
            const uint4* srch = (const uint4*)(g_wth + (size_t)g*64*88);
            const uint4* srcl = (const uint4*)(g_wtl + (size_t)g*64*88);
            uint4* dh = (uint4*)s_wh;
            uint4* dl = (uint4*)s_wl;
            for (int i = t; i < 704; i += 256) { dh[i] = srch[i]; dl[i] = srcl[i]; }
        }
        // sampler: 576 (k,p) tasks -> one STS.128 each
        const __half* gb = g_xt + ((size_t)(b*16 + g))*HW*8;
#pragma unroll
        for (int rep = 0; rep < 3; rep++) {
            int task = t + (rep << 8);
            if (task < 576) {
                int k = task >> 6, p = task & 63;
                int pix = p0 + p, y = pix >> 7, x = pix & 127;
                int ch = g*9 + k;
                float4 om = offm[(size_t)ch*HW + pix];
                float m = om.z;
                float py = (float)(y + (k/3) - 1) + om.x;
                float px = (float)(x + (k%3) - 1) + om.y;
                float fy = floorf(py), fx = floorf(px);
                float wy = py - fy, wx = px - fx;
                int y0 = (int)fy, x0 = (int)fx, y1 = y0 + 1, x1 = x0 + 1;
                float vy0 = ((unsigned)y0 < HH) ? 1.f : 0.f;
                float vy1 = ((unsigned)y1 < HH) ? 1.f : 0.f;
                float vx0 = ((unsigned)x0 < WW) ? 1.f : 0.f;
                float vx1 = ((unsigned)x1 < WW) ? 1.f : 0.f;
                int y0c = min(max(y0,0),HH-1), y1c = min(max(y1,0),HH-1);
                int x0c = min(max(x0,0),WW-1), x1c = min(max(x1,0),WW-1);
                float w00 = (1.f-wy)*(1.f-wx)*m*vy0*vx0;
                float w01 = (1.f-wy)*wx      *m*vy0*vx1;
                float w10 = wy*(1.f-wx)      *m*vy1*vx0;
                float w11 = wy*wx            *m*vy1*vx1;
                uint4 r00 = *(const uint4*)(gb + ((size_t)(y0c*WW + x0c) << 3));
                uint4 r01 = *(const uint4*)(gb + ((size_t)(y0c*WW + x1c) << 3));
                uint4 r10 = *(const uint4*)(gb + ((size_t)(y1c*WW + x0c) << 3));
                uint4 r11 = *(const uint4*)(gb + ((size_t)(y1c*WW + x1c) << 3));
                const __half2* h00 = (const __half2*)&r00;
                const __half2* h01 = (const __half2*)&r01;
                const __half2* h10 = (const __half2*)&r10;
                const __half2* h11 = (const __half2*)&r11;
                __half2 outp2[4];
#pragma unroll
                for (int i = 0; i < 4; i++) {
                    float2 f00 = __half22float2(h00[i]);
                    float2 f01 = __half22float2(h01[i]);
                    float2 f10 = __half22float2(h10[i]);
                    float2 f11 = __half22float2(h11[i]);
                    float v0 = w00*f00.x + w01*f01.x + w10*f10.x + w11*f11.x;
                    float v1 = w00*f00.y + w01*f01.y + w10*f10.y + w11*f11.y;
                    outp2[i] = __floats2half2_rn(v0, v1);
                }
                *(uint4*)(s_valT + p*88 + k*8) = *(const uint4*)outp2;
            }
        }
        __syncthreads();

        // GEMM: 5 ksteps over K=80 (cols 72..79 zero)
#pragma unroll
        for (int ks = 0; ks < 5; ks++) {
            uint32_t kOff = (uint32_t)(ks*16)*2u;
            uint32_t a_h[4], a_l[4], bv[2][4];
            ldsm_x4(a_h, sb_wh + aRow + kOff);
            ldsm_x4(a_l, sb_wl + aRow + kOff);
            ldsm_x4(bv[0], sb_val + bRow + kOff);
            ldsm_x4(bv[1], sb_val + 16*176 + bRow + kOff);
#pragma unroll
            for (int np = 0; np < 2; np++)
#pragma unroll
                for (int sub = 0; sub < 2; sub++) {
                    int nt = np*2 + sub;
                    mma_f16(acc[nt], a_h, &bv[np][sub*2]);
                    mma_f16(acc[nt], a_l, &bv[np][sub*2]);
                }
        }
    }

    float* pout = g_part + (((size_t)(q*BB + b))*64)*HW;
    int gg = lane >> 2, tq = lane & 3;
#pragma unroll
    for (int nt = 0; nt < 4; nt++)
#pragma unroll
        for (int rg = 0; rg < 4; rg++) {
            int o = warp_m*16 + gg + ((rg >> 1) ? 8 : 0);
            int p = warp_n*32 + nt*8 + tq*2 + (rg & 1);
            pout[(size_t)o*HW + p0 + p] = acc[nt][rg];
        }
}

__global__ __launch_bounds__(256) void reduce_k(const float* __restrict__ bias,
                                                float* __restrict__ out)
{
    int i = blockIdx.x*256 + threadIdx.x;
    if (i >= BB*64*HW) return;
    int pix = i & (HW - 1);
    int c   = (i >> 14) & 63;
    int b   = i >> 20;
    float s = bias[c];
#pragma unroll
    for (int q = 0; q < 4; q++)
        s += g_part[(((size_t)(q*BB + b))*64 + c)*HW + pix];
    out[i] = s;
}

// ==================== launch ====================
extern "C" void kernel_launch(void* const* d_in, const int* in_sizes, int n_in,
                              void* d_out, int out_size)
{
    const float* x   = (const float*)d_in[0];
    const float* exf = (const float*)d_in[1];
    const float* f1  = (const float*)d_in[2];
    const float* f2  = (const float*)d_in[3];
    const float* w1  = (const float*)d_in[4];
    const float* b1  = (const float*)d_in[5];
    const float* w2  = (const float*)d_in[6];
    const float* b2  = (const float*)d_in[7];
    const float* w3  = (const float*)d_in[8];
    const float* b3  = (const float*)d_in[9];
    const float* w4  = (const float*)d_in[10];
    const float* b4  = (const float*)d_in[11];
    const float* dw  = (const float*)d_in[12];
    const float* db  = (const float*)d_in[13];
    float* out = (float*)d_out;

    uint16_t *p_i0h, *p_i0l, *p_h1h, *p_h1l, *p_h2h, *p_h2l, *p_h3h, *p_h3l;
    uint16_t *p_w1h, *p_w1l, *p_w2h, *p_w2l, *p_w3h, *p_w3l, *p_w4h, *p_w4l;
    cudaGetSymbolAddress((void**)&p_i0h, g_in0h); cudaGetSymbolAddress((void**)&p_i0l, g_in0l);
    cudaGetSymbolAddress((void**)&p_h1h, g_h1h);  cudaGetSymbolAddress((void**)&p_h1l, g_h1l);
    cudaGetSymbolAddress((void**)&p_h2h, g_h2h);  cudaGetSymbolAddress((void**)&p_h2l, g_h2l);
    cudaGetSymbolAddress((void**)&p_h3h, g_h3h);  cudaGetSymbolAddress((void**)&p_h3l, g_h3l);
    cudaGetSymbolAddress((void**)&p_w1h, g_w1h);  cudaGetSymbolAddress((void**)&p_w1l, g_w1l);
    cudaGetSymbolAddress((void**)&p_w2h, g_w2h);  cudaGetSymbolAddress((void**)&p_w2l, g_w2l);
    cudaGetSymbolAddress((void**)&p_w3h, g_w3h);  cudaGetSymbolAddress((void**)&p_w3l, g_w3l);
    cudaGetSymbolAddress((void**)&p_w4h, g_w4h);  cudaGetSymbolAddress((void**)&p_w4l, g_w4l);

    const int SMTOT = 57024 + 55296;   // 112320
    cudaFuncSetAttribute(convmma_k<196,64,64,0>,  cudaFuncAttributeMaxDynamicSharedMemorySize, SMTOT);
    cudaFuncSetAttribute(convmma_k<64,64,64,0>,   cudaFuncAttributeMaxDynamicSharedMemorySize, SMTOT);
    cudaFuncSetAttribute(convmma_k<64,448,432,1>, cudaFuncAttributeMaxDynamicSharedMemorySize, SMTOT);

    pack_in0_k<<<dim3(HW/64, 4, BB), 256>>>(exf, f1, f2);
    transp_x_k<<<dim3(HW/256, 16, BB), 256>>>(x);
    wdcn_k<<<(16*64*88 + 255)/256, 256>>>(dw);
    wprep_k<<<(36*64*72  + 255)/256, 256>>>(w1, 196, 64, 64, 36, p_w1h, p_w1l);
    wprep_k<<<(9*64*72   + 255)/256, 256>>>(w2,  64, 64, 64,  9, p_w2h, p_w2l);
    wprep_k<<<(9*64*72   + 255)/256, 256>>>(w3,  64, 64, 64,  9, p_w3h, p_w3l);
    wprep_k<<<(9*448*72  + 255)/256, 256>>>(w4,  64, 432, 448, 9, p_w4h, p_w4l);

    convmma_k<196,64,64,0> <<<dim3(BB*256, 1), 256, SMTOT>>>(p_i0h, p_i0l, p_w1h, p_w1l, b1, p_h1h, p_h1l, nullptr, nullptr);
    convmma_k<64,64,64,0>  <<<dim3(BB*256, 1), 256, SMTOT>>>(p_h1h, p_h1l, p_w2h, p_w2l, b2, p_h2h, p_h2l, nullptr, nullptr);
    convmma_k<64,64,64,0>  <<<dim3(BB*256, 1), 256, SMTOT>>>(p_h2h, p_h2l, p_w3h, p_w3l, b3, p_h3h, p_h3l, nullptr, nullptr);
    convmma_k<64,448,432,1><<<dim3(BB*256, 7), 256, SMTOT>>>(p_h3h, p_h3l, p_w4h, p_w4l, b4, nullptr, nullptr, f1, f2);

    dcn4_k<<<dim3(256, BB, 4), 256>>>();
    reduce_k<<<(BB*64*HW + 255)/256, 256>>>(db, out);
}